// round 7
// baseline (speedup 1.0000x reference)
#include <cuda_runtime.h>
#include <stdint.h>
#include <math.h>

#define BB 64
#define TT 2048
#define FF 64
#define HH 160
#define GG 480            // 3*H
#define BT (BB*TT)        // 131072

typedef unsigned long long ull;
typedef unsigned int u32;

// ---------------- scratch (device globals; allocation-free) ----------------
__device__ float g_z  [BT*FF];
__device__ float g_xg1[BT*GG];
__device__ float g_h1 [BT*HH];
__device__ float g_xg2[BT*GG];
__device__ float g_h2T[BB*HH];

// ---------------- packed f32x2 helpers ----------------
__device__ __forceinline__ ull fma2(ull a, ull b, ull c) {
    ull d;
    asm("fma.rn.f32x2 %0, %1, %2, %3;" : "=l"(d) : "l"(a), "l"(b), "l"(c));
    return d;
}
__device__ __forceinline__ float f2sum(ull u) {
    float x, y;
    asm("mov.b64 {%0,%1}, %2;" : "=f"(x), "=f"(y) : "l"(u));
    return x + y;
}
__device__ __forceinline__ ull fpack(float lo, float hi) {
    ull p;
    asm("mov.b64 %0, {%1,%2};" : "=l"(p) : "f"(lo), "f"(hi));
    return p;
}

__device__ __forceinline__ float fsig(float x) {
    return __fdividef(1.f, 1.f + __expf(-x));
}
__device__ __forceinline__ float ftanh(float x) {
    return __fdividef(2.f, 1.f + __expf(-2.f * x)) - 1.f;
}

// ============================================================================
// K1: dilated conv (k=3, dil=2, pad=2) + batchnorm(inference) + exact GELU
// ============================================================================
#define K1_TT 32
__global__ void k1_conv(const float* __restrict__ x, const float* __restrict__ mix_w,
                        const float* __restrict__ bn_g, const float* __restrict__ bn_b,
                        const float* __restrict__ bn_m, const float* __restrict__ bn_v)
{
    extern __shared__ float sm[];
    float* ws = sm;                    // [3][64][64] : ws[(k*64+i)*64+f]
    float* xs = sm + 3*64*64;          // [36][64]
    const int b  = blockIdx.y;
    const int t0 = blockIdx.x * K1_TT;
    const int tid = threadIdx.x;       // 256 threads

    for (int idx = tid; idx < FF*FF*3; idx += 256) {
        int f = idx / 192; int rem = idx - f*192; int i = rem / 3; int k = rem - i*3;
        ws[(k*64 + i)*64 + f] = mix_w[idx];
    }
    for (int idx = tid; idx < 36*64; idx += 256) {
        int r = idx >> 6; int i = idx & 63;
        int t = t0 - 2 + r;
        xs[idx] = (t >= 0 && t < TT) ? x[((b*TT) + t)*64 + i] : 0.f;
    }
    __syncthreads();

    const int f  = tid & 63;
    const int tg = tid >> 6;
    const float sc = bn_g[f] * rsqrtf(bn_v[f] + 1e-5f);
    const float sh = bn_b[f] - bn_m[f] * sc;
    const float4* xs4 = (const float4*)xs;

    for (int m = 0; m < 8; m++) {
        int tl = tg + 4*m;
        float acc = 0.f;
        #pragma unroll
        for (int k = 0; k < 3; k++) {
            int r = tl + 2*k;
            const float* wk = ws + k*4096 + f;
            #pragma unroll
            for (int i4 = 0; i4 < 16; i4++) {
                float4 xv = xs4[r*16 + i4];
                acc += xv.x * wk[(i4*4 + 0)*64];
                acc += xv.y * wk[(i4*4 + 1)*64];
                acc += xv.z * wk[(i4*4 + 2)*64];
                acc += xv.w * wk[(i4*4 + 3)*64];
            }
        }
        float y  = acc * sc + sh;
        float zz = 0.5f * y * (1.f + erff(y * 0.70710678118654752f));
        g_z[((b*TT) + (t0 + tl))*64 + f] = zz;
    }
}
#define SMEM1 ((3*64*64 + 36*64)*4)

// ============================================================================
// K2: xg1 = g_z @ w_ih1^T + b_ih1      [BT,64] @ [64,480]  — all-reg, f32x2
// ============================================================================
__global__ __launch_bounds__(480) void k2_xproj(const float* __restrict__ w_ih,
                                                const float* __restrict__ b_ih)
{
    extern __shared__ float zs[];      // [64][64]
    const int c = threadIdx.x;

    ull wr[32];
    #pragma unroll
    for (int i = 0; i < 16; i++) {
        ulonglong2 v = *reinterpret_cast<const ulonglong2*>(w_ih + c*64 + 4*i);
        wr[2*i] = v.x; wr[2*i+1] = v.y;
    }
    const float bias = b_ih[c];

    const int start = blockIdx.x * 896;          // 14 tiles of 64 rows
    for (int tile = 0; tile < 14; tile++) {
        int r0 = start + tile*64;
        if (r0 >= BT) break;
        __syncthreads();
        for (int idx = c; idx < 64*16; idx += 480)
            ((float4*)zs)[idx] = ((const float4*)(g_z + (size_t)r0*64))[idx];
        __syncthreads();
        for (int r = 0; r < 64; r += 2) {
            ull a0 = 0ull, a1 = 0ull, b0 = 0ull, b1 = 0ull;
            const float* z0 = zs + r*64;
            const float* z1 = zs + r*64 + 64;
            #pragma unroll
            for (int i = 0; i < 16; i++) {
                ulonglong2 h0 = *reinterpret_cast<const ulonglong2*>(z0 + 4*i);
                ulonglong2 h1 = *reinterpret_cast<const ulonglong2*>(z1 + 4*i);
                a0 = fma2(h0.x, wr[2*i],   a0);
                a1 = fma2(h0.y, wr[2*i+1], a1);
                b0 = fma2(h1.x, wr[2*i],   b0);
                b1 = fma2(h1.y, wr[2*i+1], b1);
            }
            g_xg1[(size_t)(r0 + r    )*GG + c] = bias + f2sum(a0) + f2sum(a1);
            g_xg1[(size_t)(r0 + r + 1)*GG + c] = bias + f2sum(b0) + f2sum(b1);
        }
    }
}
#define SMEM2 (64*64*4)

// ============================================================================
// K4: xg2 = g_h1 @ w_ih2^T + b_ih2     [BT,160] @ [160,480]
//     hybrid: k<80 in regs (f32x2), k>=80 in smem as ull pairs [q][480+1]
// ============================================================================
#define K4_WS 481
__global__ __launch_bounds__(480) void k4_xproj160(const float* __restrict__ w_ih,
                                                   const float* __restrict__ b_ih)
{
    extern __shared__ __align__(16) char smraw[];
    ull*   wsm = (ull*)smraw;                      // [40][481] k-pairs for k>=80
    float* zs  = (float*)(smraw + 40*K4_WS*8);     // [16][160]
    const int c = threadIdx.x;

    for (int idx = c; idx < 480*40; idx += 480) {
        int cc = idx / 40; int q = idx - cc*40;
        float lo = w_ih[cc*160 + 80 + 2*q];
        float hi = w_ih[cc*160 + 81 + 2*q];
        wsm[q*K4_WS + cc] = fpack(lo, hi);
    }
    ull wr[40];
    #pragma unroll
    for (int i = 0; i < 20; i++) {
        ulonglong2 v = *reinterpret_cast<const ulonglong2*>(w_ih + c*160 + 4*i);
        wr[2*i] = v.x; wr[2*i+1] = v.y;
    }
    const float bias = b_ih[c];

    const int start = blockIdx.x * 896;            // 56 tiles of 16 rows
    for (int tile = 0; tile < 56; tile++) {
        int r0 = start + tile*16;
        if (r0 >= BT) break;
        __syncthreads();
        for (int idx = c; idx < 16*40; idx += 480)
            ((float4*)zs)[idx] = ((const float4*)(g_h1 + (size_t)r0*160))[idx];
        __syncthreads();
        for (int rg = 0; rg < 16; rg += 4) {
            const float* z0 = zs + (rg+0)*160;
            const float* z1 = zs + (rg+1)*160;
            const float* z2 = zs + (rg+2)*160;
            const float* z3 = zs + (rg+3)*160;
            ull a0 = 0ull, a1 = 0ull, a2 = 0ull, a3 = 0ull;
            #pragma unroll
            for (int i = 0; i < 20; i++) {
                ull wa = wr[2*i], wb = wr[2*i+1];
                ulonglong2 h;
                h = *reinterpret_cast<const ulonglong2*>(z0 + 4*i);
                a0 = fma2(h.x, wa, a0); a0 = fma2(h.y, wb, a0);
                h = *reinterpret_cast<const ulonglong2*>(z1 + 4*i);
                a1 = fma2(h.x, wa, a1); a1 = fma2(h.y, wb, a1);
                h = *reinterpret_cast<const ulonglong2*>(z2 + 4*i);
                a2 = fma2(h.x, wa, a2); a2 = fma2(h.y, wb, a2);
                h = *reinterpret_cast<const ulonglong2*>(z3 + 4*i);
                a3 = fma2(h.x, wa, a3); a3 = fma2(h.y, wb, a3);
            }
            #pragma unroll
            for (int i = 0; i < 20; i++) {
                ull wa = wsm[(2*i  )*K4_WS + c];
                ull wb = wsm[(2*i+1)*K4_WS + c];
                ulonglong2 h;
                h = *reinterpret_cast<const ulonglong2*>(z0 + 80 + 4*i);
                a0 = fma2(h.x, wa, a0); a0 = fma2(h.y, wb, a0);
                h = *reinterpret_cast<const ulonglong2*>(z1 + 80 + 4*i);
                a1 = fma2(h.x, wa, a1); a1 = fma2(h.y, wb, a1);
                h = *reinterpret_cast<const ulonglong2*>(z2 + 80 + 4*i);
                a2 = fma2(h.x, wa, a2); a2 = fma2(h.y, wb, a2);
                h = *reinterpret_cast<const ulonglong2*>(z3 + 80 + 4*i);
                a3 = fma2(h.x, wa, a3); a3 = fma2(h.y, wb, a3);
            }
            g_xg2[(size_t)(r0 + rg    )*GG + c] = bias + f2sum(a0);
            g_xg2[(size_t)(r0 + rg + 1)*GG + c] = bias + f2sum(a1);
            g_xg2[(size_t)(r0 + rg + 2)*GG + c] = bias + f2sum(a2);
            g_xg2[(size_t)(r0 + rg + 3)*GG + c] = bias + f2sum(a3);
        }
    }
}
#define SMEM4 (40*K4_WS*8 + 16*160*4)

// ============================================================================
// K3: GRU recurrence, ONE CTA per batch element (64 CTAs, no cluster).
//     Thread g owns gate row g (480 rows). Weights hybrid:
//       k<80  -> 40 f32x2 pairs in REGISTERS
//       k>=80 -> pre-paired ull in smem [40][481], LDS.64 conflict-free
//     h double-buffered in smem; fma.rn.f32x2 throughout.
// ============================================================================
#define GRU_WS 481
__global__ __launch_bounds__(480, 1) void k_gru(const float* __restrict__ w_hh,
                                                const float* __restrict__ b_hh,
                                                int which)
{
    extern __shared__ __align__(16) char smraw[];
    ull* wsm = (ull*)smraw;                         // [40][GRU_WS]
    __shared__ __align__(16) float h_s[2][HH];
    __shared__ float hp[GG];

    const int g = threadIdx.x;
    const int b = blockIdx.x;

    // stage smem half: pair (80+2q, 81+2q) for row cc
    for (int idx = g; idx < GG*40; idx += GG) {
        int cc = idx / 40; int q = idx - cc*40;
        wsm[q*GRU_WS + cc] = fpack(w_hh[cc*160 + 80 + 2*q], w_hh[cc*160 + 81 + 2*q]);
    }
    // reg half k<80
    ull wr[40];
    #pragma unroll
    for (int i = 0; i < 20; i++) {
        ulonglong2 v = *reinterpret_cast<const ulonglong2*>(w_hh + g*160 + 4*i);
        wr[2*i] = v.x; wr[2*i+1] = v.y;
    }
    const float bias = b_hh[g];
    if (g < HH) h_s[0][g] = 0.f;
    __syncthreads();

    const float* __restrict__ xgb = (which ? g_xg2 : g_xg1) + (size_t)b * TT * GG;

    float xr = 0.f, xz = 0.f, xn = 0.f;
    if (g < HH) {
        xr = xgb[      g];
        xz = xgb[160 + g];
        xn = xgb[320 + g];
    }

    for (int t = 0; t < TT; t++) {
        const int buf = t & 1;
        const float* hb = h_s[buf];

        ull a0 = 0ull, a1 = 0ull;
        #pragma unroll
        for (int q = 0; q < 20; q++) {               // reg half (k<80)
            ulonglong2 hv = *reinterpret_cast<const ulonglong2*>(hb + 4*q);
            a0 = fma2(hv.x, wr[2*q],   a0);
            a1 = fma2(hv.y, wr[2*q+1], a1);
        }
        #pragma unroll
        for (int q = 0; q < 20; q++) {               // smem half (k>=80)
            ulonglong2 hv = *reinterpret_cast<const ulonglong2*>(hb + 80 + 4*q);
            a0 = fma2(hv.x, wsm[(2*q  )*GRU_WS + g], a0);
            a1 = fma2(hv.y, wsm[(2*q+1)*GRU_WS + g], a1);
        }
        hp[g] = f2sum(a0) + f2sum(a1) + bias;
        __syncthreads();

        if (g < HH) {
            float cxr = xr, cxz = xz, cxn = xn;
            if (t + 1 < TT) {                        // prefetch next step
                const float* nx = xgb + (size_t)(t+1)*GG;
                xr = nx[      g];
                xz = nx[160 + g];
                xn = nx[320 + g];
            }
            float r  = fsig(cxr + hp[g]);
            float u  = fsig(cxz + hp[160 + g]);
            float n  = ftanh(cxn + r * hp[320 + g]);
            float hn = (1.f - u) * n + u * hb[g];
            h_s[buf ^ 1][g] = hn;
            if (!which) g_h1[(size_t)(b*TT + t)*HH + g] = hn;
        }
        __syncthreads();
    }

    if (which && g < HH) g_h2T[b*HH + g] = h_s[0][g];   // TT even -> buf 0
}
#define SMEMG (40*GRU_WS*8)

// ============================================================================
// K5: head
// ============================================================================
__global__ void k_head(const float* __restrict__ hw1, const float* __restrict__ hb1,
                       const float* __restrict__ hw2, const float* __restrict__ hb2,
                       float* __restrict__ out)
{
    __shared__ float q[80];
    const int b = blockIdx.x;
    const int j = threadIdx.x;
    const float* h = g_h2T + b*HH;
    if (j < 80) {
        float acc = hb1[j];
        #pragma unroll 4
        for (int k = 0; k < 160; k++) acc += h[k] * hw1[j*160 + k];
        q[j] = 0.5f * acc * (1.f + erff(acc * 0.70710678118654752f));
    }
    __syncthreads();
    if (j < 2) {
        float o = hb2[j];
        #pragma unroll 4
        for (int k = 0; k < 80; k++) o += q[k] * hw2[j*80 + k];
        out[b*2 + j] = o;
    }
}

// ============================================================================
extern "C" void kernel_launch(void* const* d_in, const int* in_sizes, int n_in,
                              void* d_out, int out_size)
{
    const float* x     = (const float*)d_in[0];
    const float* mix_w = (const float*)d_in[1];
    const float* bn_g  = (const float*)d_in[2];
    const float* bn_b  = (const float*)d_in[3];
    const float* bn_m  = (const float*)d_in[4];
    const float* bn_v  = (const float*)d_in[5];
    const float* w_ih1 = (const float*)d_in[6];
    const float* w_hh1 = (const float*)d_in[7];
    const float* b_ih1 = (const float*)d_in[8];
    const float* b_hh1 = (const float*)d_in[9];
    const float* w_ih2 = (const float*)d_in[10];
    const float* w_hh2 = (const float*)d_in[11];
    const float* b_ih2 = (const float*)d_in[12];
    const float* b_hh2 = (const float*)d_in[13];
    const float* hw1   = (const float*)d_in[14];
    const float* hb1   = (const float*)d_in[15];
    const float* hw2   = (const float*)d_in[16];
    const float* hb2   = (const float*)d_in[17];
    float* out = (float*)d_out;

    cudaFuncSetAttribute(k1_conv,     cudaFuncAttributeMaxDynamicSharedMemorySize, SMEM1);
    cudaFuncSetAttribute(k2_xproj,    cudaFuncAttributeMaxDynamicSharedMemorySize, SMEM2);
    cudaFuncSetAttribute(k4_xproj160, cudaFuncAttributeMaxDynamicSharedMemorySize, SMEM4);
    cudaFuncSetAttribute(k_gru,       cudaFuncAttributeMaxDynamicSharedMemorySize, SMEMG);

    k1_conv<<<dim3(TT/K1_TT, BB), 256, SMEM1>>>(x, mix_w, bn_g, bn_b, bn_m, bn_v);
    k2_xproj<<<148, 480, SMEM2>>>(w_ih1, b_ih1);
    k_gru<<<BB, 480, SMEMG>>>(w_hh1, b_hh1, 0);
    k4_xproj160<<<148, 480, SMEM4>>>(w_ih2, b_ih2);
    k_gru<<<BB, 480, SMEMG>>>(w_hh2, b_hh2, 1);
    k_head<<<BB, 128>>>(hw1, hb1, hw2, hb2, out);
}

// round 12
// speedup vs baseline: 1.6835x; 1.6835x over previous
#include <cuda_runtime.h>
#include <cuda_bf16.h>
#include <stdint.h>
#include <math.h>

#define BB 64
#define TT 2048
#define FF 64
#define HH 160
#define GG 480            // 3*H
#define BT (BB*TT)        // 131072

typedef unsigned long long ull;
typedef unsigned int u32;

// ---------------- scratch (device globals; allocation-free) ----------------
__device__ float g_z  [BT*FF];
__device__ float g_xg1[BT*GG];
__device__ float g_h1 [BT*HH];
__device__ float g_xg2[BT*GG];
__device__ float g_h2T[BB*HH];

// ---------------- packed f32x2 helpers (K2/K4 only) ----------------
__device__ __forceinline__ ull fma2(ull a, ull b, ull c) {
    ull d;
    asm("fma.rn.f32x2 %0, %1, %2, %3;" : "=l"(d) : "l"(a), "l"(b), "l"(c));
    return d;
}
__device__ __forceinline__ float f2sum(ull u) {
    float x, y;
    asm("mov.b64 {%0,%1}, %2;" : "=f"(x), "=f"(y) : "l"(u));
    return x + y;
}
__device__ __forceinline__ ull fpack(float lo, float hi) {
    ull p;
    asm("mov.b64 %0, {%1,%2};" : "=l"(p) : "f"(lo), "f"(hi));
    return p;
}

__device__ __forceinline__ float fsig(float x) {
    return __fdividef(1.f, 1.f + __expf(-x));
}
__device__ __forceinline__ float ftanh(float x) {
    return __fdividef(2.f, 1.f + __expf(-2.f * x)) - 1.f;
}

// bf16-pair unpack (bit tricks only; no cvt needed)
__device__ __forceinline__ float bflo(u32 u) { return __uint_as_float(u << 16); }
__device__ __forceinline__ float bfhi(u32 u) { return __uint_as_float(u & 0xffff0000u); }

// ============================================================================
// K1: dilated conv (k=3, dil=2, pad=2) + batchnorm(inference) + exact GELU
// ============================================================================
#define K1_TT 32
__global__ void k1_conv(const float* __restrict__ x, const float* __restrict__ mix_w,
                        const float* __restrict__ bn_g, const float* __restrict__ bn_b,
                        const float* __restrict__ bn_m, const float* __restrict__ bn_v)
{
    extern __shared__ float sm[];
    float* ws = sm;                    // [3][64][64] : ws[(k*64+i)*64+f]
    float* xs = sm + 3*64*64;          // [36][64]
    const int b  = blockIdx.y;
    const int t0 = blockIdx.x * K1_TT;
    const int tid = threadIdx.x;       // 256 threads

    for (int idx = tid; idx < FF*FF*3; idx += 256) {
        int f = idx / 192; int rem = idx - f*192; int i = rem / 3; int k = rem - i*3;
        ws[(k*64 + i)*64 + f] = mix_w[idx];
    }
    for (int idx = tid; idx < 36*64; idx += 256) {
        int r = idx >> 6; int i = idx & 63;
        int t = t0 - 2 + r;
        xs[idx] = (t >= 0 && t < TT) ? x[((b*TT) + t)*64 + i] : 0.f;
    }
    __syncthreads();

    const int f  = tid & 63;
    const int tg = tid >> 6;
    const float sc = bn_g[f] * rsqrtf(bn_v[f] + 1e-5f);
    const float sh = bn_b[f] - bn_m[f] * sc;
    const float4* xs4 = (const float4*)xs;

    for (int m = 0; m < 8; m++) {
        int tl = tg + 4*m;
        float acc = 0.f;
        #pragma unroll
        for (int k = 0; k < 3; k++) {
            int r = tl + 2*k;
            const float* wk = ws + k*4096 + f;
            #pragma unroll
            for (int i4 = 0; i4 < 16; i4++) {
                float4 xv = xs4[r*16 + i4];
                acc += xv.x * wk[(i4*4 + 0)*64];
                acc += xv.y * wk[(i4*4 + 1)*64];
                acc += xv.z * wk[(i4*4 + 2)*64];
                acc += xv.w * wk[(i4*4 + 3)*64];
            }
        }
        float y  = acc * sc + sh;
        float zz = 0.5f * y * (1.f + erff(y * 0.70710678118654752f));
        g_z[((b*TT) + (t0 + tl))*64 + f] = zz;
    }
}
#define SMEM1 ((3*64*64 + 36*64)*4)

// ============================================================================
// K2: xg1 = g_z @ w_ih1^T + b_ih1      [BT,64] @ [64,480]  — all-reg, f32x2
// ============================================================================
__global__ __launch_bounds__(480) void k2_xproj(const float* __restrict__ w_ih,
                                                const float* __restrict__ b_ih)
{
    extern __shared__ float zs[];      // [64][64]
    const int c = threadIdx.x;

    ull wr[32];
    #pragma unroll
    for (int i = 0; i < 16; i++) {
        ulonglong2 v = *reinterpret_cast<const ulonglong2*>(w_ih + c*64 + 4*i);
        wr[2*i] = v.x; wr[2*i+1] = v.y;
    }
    const float bias = b_ih[c];

    const int start = blockIdx.x * 896;          // 14 tiles of 64 rows
    for (int tile = 0; tile < 14; tile++) {
        int r0 = start + tile*64;
        if (r0 >= BT) break;
        __syncthreads();
        for (int idx = c; idx < 64*16; idx += 480)
            ((float4*)zs)[idx] = ((const float4*)(g_z + (size_t)r0*64))[idx];
        __syncthreads();
        for (int r = 0; r < 64; r += 2) {
            ull a0 = 0ull, a1 = 0ull, b0 = 0ull, b1 = 0ull;
            const float* z0 = zs + r*64;
            const float* z1 = zs + r*64 + 64;
            #pragma unroll
            for (int i = 0; i < 16; i++) {
                ulonglong2 h0 = *reinterpret_cast<const ulonglong2*>(z0 + 4*i);
                ulonglong2 h1 = *reinterpret_cast<const ulonglong2*>(z1 + 4*i);
                a0 = fma2(h0.x, wr[2*i],   a0);
                a1 = fma2(h0.y, wr[2*i+1], a1);
                b0 = fma2(h1.x, wr[2*i],   b0);
                b1 = fma2(h1.y, wr[2*i+1], b1);
            }
            g_xg1[(size_t)(r0 + r    )*GG + c] = bias + f2sum(a0) + f2sum(a1);
            g_xg1[(size_t)(r0 + r + 1)*GG + c] = bias + f2sum(b0) + f2sum(b1);
        }
    }
}
#define SMEM2 (64*64*4)

// ============================================================================
// K4: xg2 = g_h1 @ w_ih2^T + b_ih2     [BT,160] @ [160,480]
//     hybrid: k<80 in regs (f32x2), k>=80 in smem as ull pairs [q][480+1]
// ============================================================================
#define K4_WS 481
__global__ __launch_bounds__(480) void k4_xproj160(const float* __restrict__ w_ih,
                                                   const float* __restrict__ b_ih)
{
    extern __shared__ __align__(16) char smraw[];
    ull*   wsm = (ull*)smraw;                      // [40][481] k-pairs for k>=80
    float* zs  = (float*)(smraw + 40*K4_WS*8);     // [16][160]
    const int c = threadIdx.x;

    for (int idx = c; idx < 480*40; idx += 480) {
        int cc = idx / 40; int q = idx - cc*40;
        float lo = w_ih[cc*160 + 80 + 2*q];
        float hi = w_ih[cc*160 + 81 + 2*q];
        wsm[q*K4_WS + cc] = fpack(lo, hi);
    }
    ull wr[40];
    #pragma unroll
    for (int i = 0; i < 20; i++) {
        ulonglong2 v = *reinterpret_cast<const ulonglong2*>(w_ih + c*160 + 4*i);
        wr[2*i] = v.x; wr[2*i+1] = v.y;
    }
    const float bias = b_ih[c];

    const int start = blockIdx.x * 896;            // 56 tiles of 16 rows
    for (int tile = 0; tile < 56; tile++) {
        int r0 = start + tile*16;
        if (r0 >= BT) break;
        __syncthreads();
        for (int idx = c; idx < 16*40; idx += 480)
            ((float4*)zs)[idx] = ((const float4*)(g_h1 + (size_t)r0*160))[idx];
        __syncthreads();
        for (int rg = 0; rg < 16; rg += 4) {
            const float* z0 = zs + (rg+0)*160;
            const float* z1 = zs + (rg+1)*160;
            const float* z2 = zs + (rg+2)*160;
            const float* z3 = zs + (rg+3)*160;
            ull a0 = 0ull, a1 = 0ull, a2 = 0ull, a3 = 0ull;
            #pragma unroll
            for (int i = 0; i < 20; i++) {
                ull wa = wr[2*i], wb = wr[2*i+1];
                ulonglong2 h;
                h = *reinterpret_cast<const ulonglong2*>(z0 + 4*i);
                a0 = fma2(h.x, wa, a0); a0 = fma2(h.y, wb, a0);
                h = *reinterpret_cast<const ulonglong2*>(z1 + 4*i);
                a1 = fma2(h.x, wa, a1); a1 = fma2(h.y, wb, a1);
                h = *reinterpret_cast<const ulonglong2*>(z2 + 4*i);
                a2 = fma2(h.x, wa, a2); a2 = fma2(h.y, wb, a2);
                h = *reinterpret_cast<const ulonglong2*>(z3 + 4*i);
                a3 = fma2(h.x, wa, a3); a3 = fma2(h.y, wb, a3);
            }
            #pragma unroll
            for (int i = 0; i < 20; i++) {
                ull wa = wsm[(2*i  )*K4_WS + c];
                ull wb = wsm[(2*i+1)*K4_WS + c];
                ulonglong2 h;
                h = *reinterpret_cast<const ulonglong2*>(z0 + 80 + 4*i);
                a0 = fma2(h.x, wa, a0); a0 = fma2(h.y, wb, a0);
                h = *reinterpret_cast<const ulonglong2*>(z1 + 80 + 4*i);
                a1 = fma2(h.x, wa, a1); a1 = fma2(h.y, wb, a1);
                h = *reinterpret_cast<const ulonglong2*>(z2 + 80 + 4*i);
                a2 = fma2(h.x, wa, a2); a2 = fma2(h.y, wb, a2);
                h = *reinterpret_cast<const ulonglong2*>(z3 + 80 + 4*i);
                a3 = fma2(h.x, wa, a3); a3 = fma2(h.y, wb, a3);
            }
            g_xg2[(size_t)(r0 + rg    )*GG + c] = bias + f2sum(a0);
            g_xg2[(size_t)(r0 + rg + 1)*GG + c] = bias + f2sum(a1);
            g_xg2[(size_t)(r0 + rg + 2)*GG + c] = bias + f2sum(a2);
            g_xg2[(size_t)(r0 + rg + 3)*GG + c] = bias + f2sum(a3);
        }
    }
}
#define SMEM4 (40*K4_WS*8 + 16*160*4)

// ============================================================================
// K3: GRU recurrence, ONE CTA per batch element (64 CTAs, no cluster).
//     Thread g owns gate row g. Weights:
//       k<80  -> 80 SCALAR fp32 registers (R1-proven, no pair pressure)
//       k>=80 -> bf16 PAIRS in smem [40][481] u32, LDS.32 conflict-free
//                (halves smem weight bytes: 1200 -> 600 wf/step)
//     fp32 h, fp32 accumulate (4 accumulators for FFMA ILP).
// ============================================================================
#define GRU_WS 481
__global__ __launch_bounds__(480, 1) void k_gru(const float* __restrict__ w_hh,
                                                const float* __restrict__ b_hh,
                                                int which)
{
    __shared__ __align__(16) u32  wsm[40*GRU_WS];   // bf16 pairs, k>=80
    __shared__ __align__(16) float h_s[2][HH];
    __shared__ float hp[GG];

    const int g = threadIdx.x;
    const int b = blockIdx.x;

    // stage smem half as bf16 pairs: pair p covers k = 80+2p, 81+2p for row cc
    for (int idx = g; idx < GG*40; idx += GG) {
        int cc = idx / 40; int p = idx - cc*40;
        __nv_bfloat162 pr = __floats2bfloat162_rn(w_hh[cc*160 + 80 + 2*p],
                                                  w_hh[cc*160 + 81 + 2*p]);
        wsm[p*GRU_WS + cc] = *reinterpret_cast<u32*>(&pr);
    }
    // reg half k<80: scalar fp32 (one-time strided LDG, L2-resident weights)
    float wreg[80];
    #pragma unroll
    for (int k = 0; k < 80; k++) wreg[k] = w_hh[g*160 + k];
    const float bias = b_hh[g];
    if (g < HH) h_s[0][g] = 0.f;
    __syncthreads();

    const float* __restrict__ xgb = (which ? g_xg2 : g_xg1) + (size_t)b * TT * GG;

    float xr = 0.f, xz = 0.f, xn = 0.f;
    if (g < HH) {
        xr = xgb[      g];
        xz = xgb[160 + g];
        xn = xgb[320 + g];
    }

    for (int t = 0; t < TT; t++) {
        const int buf = t & 1;
        const float4* hb4 = (const float4*)h_s[buf];

        float a0 = 0.f, a1 = 0.f, a2 = 0.f, a3 = 0.f;
        #pragma unroll
        for (int i = 0; i < 20; i++) {               // reg half (k<80)
            float4 hv = hb4[i];
            a0 += hv.x * wreg[4*i+0];
            a1 += hv.y * wreg[4*i+1];
            a2 += hv.z * wreg[4*i+2];
            a3 += hv.w * wreg[4*i+3];
        }
        #pragma unroll
        for (int i = 0; i < 20; i++) {               // smem half (k>=80), bf16 pairs
            float4 hv = hb4[20 + i];
            u32 u0 = wsm[(2*i  )*GRU_WS + g];
            u32 u1 = wsm[(2*i+1)*GRU_WS + g];
            a0 += hv.x * bflo(u0);
            a1 += hv.y * bfhi(u0);
            a2 += hv.z * bflo(u1);
            a3 += hv.w * bfhi(u1);
        }
        hp[g] = (a0 + a1) + (a2 + a3) + bias;
        __syncthreads();

        if (g < HH) {
            float cxr = xr, cxz = xz, cxn = xn;
            if (t + 1 < TT) {                        // prefetch next step
                const float* nx = xgb + (size_t)(t+1)*GG;
                xr = nx[      g];
                xz = nx[160 + g];
                xn = nx[320 + g];
            }
            float r  = fsig(cxr + hp[g]);
            float u  = fsig(cxz + hp[160 + g]);
            float n  = ftanh(cxn + r * hp[320 + g]);
            float hn = (1.f - u) * n + u * h_s[buf][g];
            h_s[buf ^ 1][g] = hn;
            if (!which) g_h1[(size_t)(b*TT + t)*HH + g] = hn;
        }
        __syncthreads();
    }

    if (which && g < HH) g_h2T[b*HH + g] = h_s[0][g];   // TT even -> buf 0
}

// ============================================================================
// K5: head
// ============================================================================
__global__ void k_head(const float* __restrict__ hw1, const float* __restrict__ hb1,
                       const float* __restrict__ hw2, const float* __restrict__ hb2,
                       float* __restrict__ out)
{
    __shared__ float q[80];
    const int b = blockIdx.x;
    const int j = threadIdx.x;
    const float* h = g_h2T + b*HH;
    if (j < 80) {
        float acc = hb1[j];
        #pragma unroll 4
        for (int k = 0; k < 160; k++) acc += h[k] * hw1[j*160 + k];
        q[j] = 0.5f * acc * (1.f + erff(acc * 0.70710678118654752f));
    }
    __syncthreads();
    if (j < 2) {
        float o = hb2[j];
        #pragma unroll 4
        for (int k = 0; k < 80; k++) o += q[k] * hw2[j*80 + k];
        out[b*2 + j] = o;
    }
}

// ============================================================================
extern "C" void kernel_launch(void* const* d_in, const int* in_sizes, int n_in,
                              void* d_out, int out_size)
{
    const float* x     = (const float*)d_in[0];
    const float* mix_w = (const float*)d_in[1];
    const float* bn_g  = (const float*)d_in[2];
    const float* bn_b  = (const float*)d_in[3];
    const float* bn_m  = (const float*)d_in[4];
    const float* bn_v  = (const float*)d_in[5];
    const float* w_ih1 = (const float*)d_in[6];
    const float* w_hh1 = (const float*)d_in[7];
    const float* b_ih1 = (const float*)d_in[8];
    const float* b_hh1 = (const float*)d_in[9];
    const float* w_ih2 = (const float*)d_in[10];
    const float* w_hh2 = (const float*)d_in[11];
    const float* b_ih2 = (const float*)d_in[12];
    const float* b_hh2 = (const float*)d_in[13];
    const float* hw1   = (const float*)d_in[14];
    const float* hb1   = (const float*)d_in[15];
    const float* hw2   = (const float*)d_in[16];
    const float* hb2   = (const float*)d_in[17];
    float* out = (float*)d_out;

    cudaFuncSetAttribute(k1_conv,     cudaFuncAttributeMaxDynamicSharedMemorySize, SMEM1);
    cudaFuncSetAttribute(k2_xproj,    cudaFuncAttributeMaxDynamicSharedMemorySize, SMEM2);
    cudaFuncSetAttribute(k4_xproj160, cudaFuncAttributeMaxDynamicSharedMemorySize, SMEM4);

    k1_conv<<<dim3(TT/K1_TT, BB), 256, SMEM1>>>(x, mix_w, bn_g, bn_b, bn_m, bn_v);
    k2_xproj<<<148, 480, SMEM2>>>(w_ih1, b_ih1);
    k_gru<<<BB, 480>>>(w_hh1, b_hh1, 0);
    k4_xproj160<<<148, 480, SMEM4>>>(w_ih2, b_ih2);
    k_gru<<<BB, 480>>>(w_hh2, b_hh2, 1);
    k_head<<<BB, 128>>>(hw1, hb1, hw2, hb2, out);
}